// round 5
// baseline (speedup 1.0000x reference)
#include <cuda_runtime.h>
#include <cuda_fp16.h>
#include <cstdint>

#define DI __device__ __forceinline__

static constexpr int CIN = 512, CMID = 1024, CO2 = 425, NPOS = 1024;

// ---------------- device scratch (fp16 hi/lo splits) ----------------
__device__ __half g_a_h[(size_t)32 * NPOS * CIN];
__device__ __half g_a_l[(size_t)32 * NPOS * CIN];
__device__ __half g_x_h[(size_t)32 * NPOS * CMID];
__device__ __half g_x_l[(size_t)32 * NPOS * CMID];
__device__ __half g_w1_h[(size_t)9 * CMID * CIN];
__device__ __half g_w1_l[(size_t)9 * CMID * CIN];
__device__ __half g_w2_h[(size_t)512 * CMID];
__device__ __half g_w2_l[(size_t)512 * CMID];
__device__ float  g_preds[(size_t)32 * NPOS * 512];

__constant__ float c_anc_w[5] = {42.f, 98.f, 180.f, 300.f, 400.f};
__constant__ float c_anc_h[5] = {45.f, 130.f, 260.f, 180.f, 400.f};

// ---------------- PTX helpers (baseline sm_80-class) ----------------
DI uint32_t smem_u32(const void* p) {
    uint32_t a;
    asm("{ .reg .u64 t; cvta.to.shared.u64 t, %1; cvt.u32.u64 %0, t; }" : "=r"(a) : "l"(p));
    return a;
}
DI void cp16(uint32_t dst, const void* src, uint32_t nbytes) {
    asm volatile("cp.async.cg.shared.global [%0], [%1], 16, %2;"
                 :: "r"(dst), "l"(src), "r"(nbytes) : "memory");
}
DI void cp_commit() { asm volatile("cp.async.commit_group;" ::: "memory"); }
template <int N> DI void cp_wait() {
    asm volatile("cp.async.wait_group %0;" :: "n"(N) : "memory");
}
DI void ldm4(uint32_t a, uint32_t& r0, uint32_t& r1, uint32_t& r2, uint32_t& r3) {
    asm volatile("ldmatrix.sync.aligned.m8n8.x4.shared.b16 {%0,%1,%2,%3}, [%4];"
                 : "=r"(r0), "=r"(r1), "=r"(r2), "=r"(r3) : "r"(a));
}
DI void mma16816(float* c, const uint32_t* a, const uint32_t* b) {
    asm volatile(
        "mma.sync.aligned.m16n8k16.row.col.f32.f16.f16.f32 "
        "{%0,%1,%2,%3},{%4,%5,%6,%7},{%8,%9},{%0,%1,%2,%3};"
        : "+f"(c[0]), "+f"(c[1]), "+f"(c[2]), "+f"(c[3])
        : "r"(a[0]), "r"(a[1]), "r"(a[2]), "r"(a[3]), "r"(b[0]), "r"(b[1]));
}
DI uint32_t swz(uint32_t byte_off, int rl) {  // XOR bit4 with bit2 of row index
    return byte_off ^ ((rl & 4) << 2);
}

// ---------------- prep kernels ----------------
__global__ void prep_x(const float* __restrict__ feat) {
    __shared__ float t[32][33];
    const int r = blockIdx.x, cit = blockIdx.y, b = blockIdx.z;
    const int col = threadIdx.x & 31, row8 = threadIdx.x >> 5;
#pragma unroll
    for (int it = 0; it < 4; it++) {
        int ci_l = row8 + it * 8;
        t[ci_l][col] = feat[(((size_t)b * CIN + cit * 32 + ci_l) * 32 + r) * 32 + col];
    }
    __syncthreads();
    const int ci = threadIdx.x & 31;
#pragma unroll
    for (int it = 0; it < 4; it++) {
        int cc = (threadIdx.x >> 5) + it * 8;
        float v = t[ci][cc];
        __half hi = __float2half_rn(v);
        __half lo = __float2half_rn(v - __half2float(hi));
        size_t o = ((size_t)b * NPOS + r * 32 + cc) * CIN + cit * 32 + ci;
        g_a_h[o] = hi;
        g_a_l[o] = lo;
    }
}
__global__ void prep_w1(const float* __restrict__ w1) {
    int t = blockIdx.x * 256 + threadIdx.x;  // 1024*512
    int co = t >> 9, ci = t & 511;
#pragma unroll
    for (int kk = 0; kk < 9; kk++) {
        float v = w1[((size_t)co * CIN + ci) * 9 + kk];
        __half hi = __float2half_rn(v);
        __half lo = __float2half_rn(v - __half2float(hi));
        size_t o = ((size_t)kk * CMID + co) * CIN + ci;
        g_w1_h[o] = hi;
        g_w1_l[o] = lo;
    }
}
__global__ void prep_w2(const float* __restrict__ w2) {
    int t = blockIdx.x * 256 + threadIdx.x;  // 512*1024
    int co = t >> 10, ci = t & 1023;
    float v = (co < CO2) ? w2[(size_t)co * CMID + ci] : 0.f;
    __half hi = __float2half_rn(v);
    __half lo = __float2half_rn(v - __half2float(hi));
    g_w2_h[t] = hi;
    g_w2_l[t] = lo;
}

// ---------------- conv1: implicit 3x3 conv, fp16-split mma.sync -------------
// Block: M=256 pos (8 out rows x 32 cols) x N=128 co; 512 thr (16 warps 4x4).
static constexpr int C1_IN_SPLIT = 10880;       // 10*34*16*2
static constexpr int C1_WOFF = 21760;           // input total (2 splits)
static constexpr int C1_STAGE = 21760 + 73728;  // 95488
static constexpr int C1_SMEM = 2 * C1_STAGE + 1024;

__global__ void __launch_bounds__(512, 1)
conv1_mma(const float* __restrict__ gamma, const float* __restrict__ beta,
          const float* __restrict__ mean, const float* __restrict__ var) {
    extern __shared__ __align__(16) char smem[];
    const uint32_t sb = smem_u32(smem);
    const int tid = threadIdx.x, lane = tid & 31, wid = tid >> 5;
    const int b = blockIdx.z, co0 = blockIdx.y * 128, row0 = blockIdx.x * 8;
    float* s_sc = (float*)(smem + 2 * C1_STAGE);
    float* s_sh = s_sc + 128;
    if (tid < 128) {
        float sc = gamma[co0 + tid] * rsqrtf(var[co0 + tid] + 1e-5f);
        s_sc[tid] = sc;
        s_sh[tid] = beta[co0 + tid] - mean[co0 + tid] * sc;
    }
    const int warp_m0 = (wid >> 2) * 64, warp_n0 = (wid & 3) * 32;
    const int aro = ((lane >> 3) & 1) * 8 + (lane & 7);
    const int ahalf = lane >> 4;
    int Lb[4];
#pragma unroll
    for (int mf = 0; mf < 4; mf++) {
        int m = warp_m0 + mf * 16 + aro;
        Lb[mf] = (m >> 5) * 34 + (m & 31);
    }
    const int bco = ((lane >> 4) << 3) + (lane & 7);
    const int bhalf = (lane >> 3) & 1;
    const uint32_t bbase = swz((uint32_t)(bco * 32 + bhalf * 16), bco);

    float acc[4][4][4];
#pragma unroll
    for (int i = 0; i < 4; i++)
#pragma unroll
        for (int j = 0; j < 4; j++)
#pragma unroll
            for (int k = 0; k < 4; k++) acc[i][j][k] = 0.f;

    auto load_stage = [&](int s, int ci0) {
        uint32_t st = sb + s * C1_STAGE;
        // input: 2 splits x 10 rows x 34 cols x 2 halves = 1360 x 16B
#pragma unroll
        for (int it = 0; it < 3; it++) {
            int u = tid + it * 512;
            if (u < 1360) {
                int split = u >= 680;
                int r2 = u - split * 680;
                int i = r2 / 68;
                int r3 = r2 - i * 68;
                int j = r3 >> 1, half = r3 & 1;
                int ri = row0 + i - 1, cix = j - 1;
                bool ok = (unsigned)ri < 32u && (unsigned)cix < 32u;
                const __half* g = split ? g_a_l : g_a_h;
                const __half* src =
                    ok ? g + (((size_t)b * NPOS + ri * 32 + cix) * CIN + ci0 + half * 8) : g;
                int rl = i * 34 + j;
                uint32_t d = st + split * C1_IN_SPLIT +
                             swz((uint32_t)(rl * 32 + half * 16), rl);
                cp16(d, src, ok ? 16u : 0u);
            }
        }
        // weights: 9 kk x 2 splits x 128 co x 2 halves = 4608 x 16B
#pragma unroll
        for (int it = 0; it < 9; it++) {
            int u = tid + it * 512;
            int kk = u >> 9;
            int r2 = u & 511;
            int split = r2 >> 8;
            int r3 = r2 & 255;
            int co = r3 >> 1, half = r3 & 1;
            const __half* g = split ? g_w1_l : g_w1_h;
            const __half* src = g + (((size_t)kk * CMID + co0 + co) * CIN + ci0 + half * 8);
            uint32_t d = st + C1_WOFF + (kk * 2 + split) * 4096 +
                         swz((uint32_t)(co * 32 + half * 16), co);
            cp16(d, src, 16u);
        }
    };

    load_stage(0, 0);
    cp_commit();

    for (int ch = 0; ch < 32; ch++) {
        if (ch < 31) {
            load_stage((ch + 1) & 1, (ch + 1) * 16);
            cp_commit();
            cp_wait<1>();
        } else {
            cp_wait<0>();
        }
        __syncthreads();
        uint32_t st = sb + (ch & 1) * C1_STAGE;
        uint32_t areg[4][4], bregH[4][2], bregL[4][2];
#pragma unroll
        for (int kk = 0; kk < 9; kk++) {
            const int D = (kk / 3) * 34 + (kk % 3);
            // B: both splits resident (4 ldm4)
            {
                uint32_t baseH = st + C1_WOFF + (kk * 2) * 4096 + bbase;
                uint32_t baseL = baseH + 4096;
#pragma unroll
                for (int np = 0; np < 2; np++) {
                    uint32_t r0, r1, r2, r3;
                    ldm4(baseH + (uint32_t)((warp_n0 + np * 16) * 32), r0, r1, r2, r3);
                    bregH[np * 2][0] = r0; bregH[np * 2][1] = r1;
                    bregH[np * 2 + 1][0] = r2; bregH[np * 2 + 1][1] = r3;
                    ldm4(baseL + (uint32_t)((warp_n0 + np * 16) * 32), r0, r1, r2, r3);
                    bregL[np * 2][0] = r0; bregL[np * 2][1] = r1;
                    bregL[np * 2 + 1][0] = r2; bregL[np * 2 + 1][1] = r3;
                }
            }
            auto lda = [&](int split) {
                uint32_t base = st + split * C1_IN_SPLIT;
#pragma unroll
                for (int mf = 0; mf < 4; mf++) {
                    int rl = Lb[mf] + D;
                    uint32_t ad = base + swz((uint32_t)(rl * 32 + ahalf * 16), rl);
                    ldm4(ad, areg[mf][0], areg[mf][1], areg[mf][2], areg[mf][3]);
                }
            };
            lda(0);  // A-hi
#pragma unroll
            for (int mf = 0; mf < 4; mf++)
#pragma unroll
                for (int nf = 0; nf < 4; nf++) mma16816(acc[mf][nf], areg[mf], bregH[nf]);
#pragma unroll
            for (int mf = 0; mf < 4; mf++)
#pragma unroll
                for (int nf = 0; nf < 4; nf++) mma16816(acc[mf][nf], areg[mf], bregL[nf]);
            lda(1);  // A-lo
#pragma unroll
            for (int mf = 0; mf < 4; mf++)
#pragma unroll
                for (int nf = 0; nf < 4; nf++) mma16816(acc[mf][nf], areg[mf], bregH[nf]);
        }
        __syncthreads();
    }

    // epilogue: BN + leaky, write fp16 hi/lo splits for conv2
    const int gq = lane >> 2, t4 = lane & 3;
#pragma unroll
    for (int mf = 0; mf < 4; mf++) {
#pragma unroll
        for (int nf = 0; nf < 4; nf++) {
            int n = warp_n0 + nf * 8 + t4 * 2;
            float sc0 = s_sc[n], sc1 = s_sc[n + 1];
            float sh0 = s_sh[n], sh1 = s_sh[n + 1];
#pragma unroll
            for (int rr = 0; rr < 2; rr++) {
                int m = warp_m0 + mf * 16 + gq + rr * 8;
                float v0 = acc[mf][nf][rr * 2] * sc0 + sh0;
                float v1 = acc[mf][nf][rr * 2 + 1] * sc1 + sh1;
                v0 = v0 > 0.f ? v0 : 0.1f * v0;
                v1 = v1 > 0.f ? v1 : 0.1f * v1;
                __half h0 = __float2half_rn(v0), h1 = __float2half_rn(v1);
                __half l0 = __float2half_rn(v0 - __half2float(h0));
                __half l1 = __float2half_rn(v1 - __half2float(h1));
                size_t idx =
                    ((size_t)b * NPOS + blockIdx.x * 256 + m) * CMID + co0 + n;
                *(__half2*)(g_x_h + idx) = __halves2half2(h0, h1);
                *(__half2*)(g_x_l + idx) = __halves2half2(l0, l1);
            }
        }
    }
}

// ---------------- conv2: 1x1 GEMM, fp16-split mma.sync ----------------------
static constexpr int C2_IN_SPLIT = 8192;        // 256*16*2
static constexpr int C2_WOFF = 16384;
static constexpr int C2_STAGE = 16384 + 8192;   // 24576
static constexpr int C2_SMEM = 2 * C2_STAGE + 512;

__global__ void __launch_bounds__(512, 1)
conv2_mma(const float* __restrict__ b2) {
    extern __shared__ __align__(16) char smem[];
    const uint32_t sb = smem_u32(smem);
    const int tid = threadIdx.x, lane = tid & 31, wid = tid >> 5;
    const int b = blockIdx.z, co0 = blockIdx.y * 128, m0 = blockIdx.x * 256;
    float* s_bias = (float*)(smem + 2 * C2_STAGE);
    if (tid < 128) s_bias[tid] = (co0 + tid < CO2) ? b2[co0 + tid] : 0.f;

    const int warp_m0 = (wid >> 2) * 64, warp_n0 = (wid & 3) * 32;
    const int aro = ((lane >> 3) & 1) * 8 + (lane & 7);
    const int ahalf = lane >> 4;
    const int bco = ((lane >> 4) << 3) + (lane & 7);
    const int bhalf = (lane >> 3) & 1;
    const uint32_t bbase = swz((uint32_t)(bco * 32 + bhalf * 16), bco);

    float acc[4][4][4];
#pragma unroll
    for (int i = 0; i < 4; i++)
#pragma unroll
        for (int j = 0; j < 4; j++)
#pragma unroll
            for (int k = 0; k < 4; k++) acc[i][j][k] = 0.f;

    auto load_stage = [&](int s, int ci0) {
        uint32_t st = sb + s * C2_STAGE;
#pragma unroll
        for (int it = 0; it < 2; it++) {  // input: 2x256x2 = 1024 units
            int u = tid + it * 512;
            int split = u >> 9;
            int r2 = u & 511;
            int m = r2 >> 1, half = r2 & 1;
            const __half* g = split ? g_x_l : g_x_h;
            const __half* src = g + (((size_t)b * NPOS + m0 + m) * CMID + ci0 + half * 8);
            uint32_t d = st + split * C2_IN_SPLIT + swz((uint32_t)(m * 32 + half * 16), m);
            cp16(d, src, 16u);
        }
        {  // weights: 2x128x2 = 512 units
            int u = tid;
            int split = u >> 8;
            int r2 = u & 255;
            int co = r2 >> 1, half = r2 & 1;
            const __half* g = split ? g_w2_l : g_w2_h;
            const __half* src = g + ((size_t)(co0 + co) * CMID + ci0 + half * 8);
            uint32_t d = st + C2_WOFF + split * 4096 +
                         swz((uint32_t)(co * 32 + half * 16), co);
            cp16(d, src, 16u);
        }
    };

    load_stage(0, 0);
    cp_commit();

    for (int ch = 0; ch < 64; ch++) {
        if (ch < 63) {
            load_stage((ch + 1) & 1, (ch + 1) * 16);
            cp_commit();
            cp_wait<1>();
        } else {
            cp_wait<0>();
        }
        __syncthreads();
        uint32_t st = sb + (ch & 1) * C2_STAGE;
        uint32_t areg[4][4], bregH[4][2], bregL[4][2];
        {
            uint32_t baseH = st + C2_WOFF + bbase;
            uint32_t baseL = baseH + 4096;
#pragma unroll
            for (int np = 0; np < 2; np++) {
                uint32_t r0, r1, r2, r3;
                ldm4(baseH + (uint32_t)((warp_n0 + np * 16) * 32), r0, r1, r2, r3);
                bregH[np * 2][0] = r0; bregH[np * 2][1] = r1;
                bregH[np * 2 + 1][0] = r2; bregH[np * 2 + 1][1] = r3;
                ldm4(baseL + (uint32_t)((warp_n0 + np * 16) * 32), r0, r1, r2, r3);
                bregL[np * 2][0] = r0; bregL[np * 2][1] = r1;
                bregL[np * 2 + 1][0] = r2; bregL[np * 2 + 1][1] = r3;
            }
        }
        auto lda = [&](int split) {
            uint32_t base = st + split * C2_IN_SPLIT;
#pragma unroll
            for (int mf = 0; mf < 4; mf++) {
                int m = warp_m0 + mf * 16 + aro;
                uint32_t ad = base + swz((uint32_t)(m * 32 + ahalf * 16), m);
                ldm4(ad, areg[mf][0], areg[mf][1], areg[mf][2], areg[mf][3]);
            }
        };
        lda(0);
#pragma unroll
        for (int mf = 0; mf < 4; mf++)
#pragma unroll
            for (int nf = 0; nf < 4; nf++) mma16816(acc[mf][nf], areg[mf], bregH[nf]);
#pragma unroll
        for (int mf = 0; mf < 4; mf++)
#pragma unroll
            for (int nf = 0; nf < 4; nf++) mma16816(acc[mf][nf], areg[mf], bregL[nf]);
        lda(1);
#pragma unroll
        for (int mf = 0; mf < 4; mf++)
#pragma unroll
            for (int nf = 0; nf < 4; nf++) mma16816(acc[mf][nf], areg[mf], bregH[nf]);
        __syncthreads();
    }

    const int gq = lane >> 2, t4 = lane & 3;
#pragma unroll
    for (int mf = 0; mf < 4; mf++) {
#pragma unroll
        for (int nf = 0; nf < 4; nf++) {
            int n = warp_n0 + nf * 8 + t4 * 2;
            float b0 = s_bias[n], b1 = s_bias[n + 1];
#pragma unroll
            for (int rr = 0; rr < 2; rr++) {
                int m = warp_m0 + mf * 16 + gq + rr * 8;
                float v0 = acc[mf][nf][rr * 2] + b0;
                float v1 = acc[mf][nf][rr * 2 + 1] + b1;
                size_t idx = ((size_t)b * NPOS + m0 + m) * 512 + co0 + n;
                *(float2*)(g_preds + idx) = make_float2(v0, v1);
            }
        }
    }
}

// ---------------- decode ----------------
__global__ void decode_kernel(float* __restrict__ out) {
    int t = blockIdx.x * 256 + threadIdx.x;
    int p = t & 1023, ba = t >> 10, a = ba % 5, b = ba / 5;
    const float* pr = g_preds + ((size_t)b * NPOS + p) * 512 + a * 85;
    float tx = pr[0], ty = pr[1], tw = pr[2], th = pr[3], to = pr[4];
    float m = -1e30f, ssum = 0.f;
    int arg = 0;
#pragma unroll 4
    for (int j = 0; j < 80; j++) {
        float l = pr[5 + j];
        if (l > m) { ssum = ssum * expf(m - l) + 1.f; m = l; arg = j; }
        else        ssum += expf(l - m);
    }
    float obj = 1.f / (1.f + expf(-to));
    float score = obj / ssum;
    float bx = 1.f / (1.f + expf(-tx));
    float by = 1.f / (1.f + expf(-ty));
    float bw = expf(fminf(tw, 8.f));
    float bh = expf(fminf(th, 8.f));
    float cx = (bx + (float)(p & 31)) * 32.f;
    float cy = (by + (float)(p >> 5)) * 32.f;
    float pw = c_anc_w[a] * bw, ph = c_anc_h[a] * bh;
    float x1 = fminf(fmaxf(cx - 0.5f * pw, 0.f), 1023.f);
    float y1 = fminf(fmaxf(cy - 0.5f * ph, 0.f), 1023.f);
    float x2 = fminf(fmaxf(cx + 0.5f * pw, 0.f), 1023.f);
    float y2 = fminf(fmaxf(cy + 0.5f * ph, 0.f), 1023.f);
    size_t n = (size_t)b * 5120 + (size_t)p * 5 + a;
    float* o5 = out + n * 5;
    o5[0] = x1; o5[1] = y1; o5[2] = x2; o5[3] = y2; o5[4] = score;
    out[(size_t)819200 + n] = (float)arg;
}

// ---------------- host ----------------
extern "C" void kernel_launch(void* const* d_in, const int* in_sizes, int n_in,
                              void* d_out, int out_size) {
    const float* feat = (const float*)d_in[0];
    const float* w1   = (const float*)d_in[1];
    const float* gam  = (const float*)d_in[2];
    const float* bet  = (const float*)d_in[3];
    const float* mean = (const float*)d_in[4];
    const float* var  = (const float*)d_in[5];
    const float* w2   = (const float*)d_in[6];
    const float* b2   = (const float*)d_in[7];
    float* out = (float*)d_out;

    static bool attr_done = false;
    if (!attr_done) {
        cudaFuncSetAttribute(conv1_mma, cudaFuncAttributeMaxDynamicSharedMemorySize, C1_SMEM);
        cudaFuncSetAttribute(conv2_mma, cudaFuncAttributeMaxDynamicSharedMemorySize, C2_SMEM);
        attr_done = true;
    }

    prep_x<<<dim3(32, 16, 32), 256>>>(feat);
    prep_w1<<<2048, 256>>>(w1);
    prep_w2<<<2048, 256>>>(w2);
    conv1_mma<<<dim3(4, 8, 32), 512, C1_SMEM>>>(gam, bet, mean, var);
    conv2_mma<<<dim3(4, 4, 32), 512, C2_SMEM>>>(b2);
    decode_kernel<<<640, 256>>>(out);
}

// round 6
// speedup vs baseline: 1.0765x; 1.0765x over previous
#include <cuda_runtime.h>
#include <cuda_fp16.h>
#include <cstdint>

#define DI __device__ __forceinline__

static constexpr int CIN = 512, CMID = 1024, CO2 = 425, NPOS = 1024;

// ---------------- device scratch (fp16 hi/lo splits) ----------------
__device__ __half g_a_h[(size_t)32 * NPOS * CIN];
__device__ __half g_a_l[(size_t)32 * NPOS * CIN];
__device__ __half g_x_h[(size_t)32 * NPOS * CMID];
__device__ __half g_x_l[(size_t)32 * NPOS * CMID];
__device__ __half g_w1_h[(size_t)9 * CMID * CIN];
__device__ __half g_w1_l[(size_t)9 * CMID * CIN];
__device__ __half g_w2_h[(size_t)512 * CMID];
__device__ __half g_w2_l[(size_t)512 * CMID];
__device__ float  g_preds[(size_t)32 * NPOS * 512];

__constant__ float c_anc_w[5] = {42.f, 98.f, 180.f, 300.f, 400.f};
__constant__ float c_anc_h[5] = {45.f, 130.f, 260.f, 180.f, 400.f};

// ---------------- PTX helpers (baseline sm_80-class) ----------------
DI uint32_t smem_u32(const void* p) {
    uint32_t a;
    asm("{ .reg .u64 t; cvta.to.shared.u64 t, %1; cvt.u32.u64 %0, t; }" : "=r"(a) : "l"(p));
    return a;
}
DI void cp16(uint32_t dst, const void* src, uint32_t nbytes) {
    asm volatile("cp.async.cg.shared.global [%0], [%1], 16, %2;"
                 :: "r"(dst), "l"(src), "r"(nbytes) : "memory");
}
DI void cp_commit() { asm volatile("cp.async.commit_group;" ::: "memory"); }
template <int N> DI void cp_wait() {
    asm volatile("cp.async.wait_group %0;" :: "n"(N) : "memory");
}
DI void ldm4(uint32_t a, uint32_t& r0, uint32_t& r1, uint32_t& r2, uint32_t& r3) {
    asm volatile("ldmatrix.sync.aligned.m8n8.x4.shared.b16 {%0,%1,%2,%3}, [%4];"
                 : "=r"(r0), "=r"(r1), "=r"(r2), "=r"(r3) : "r"(a));
}
DI void mma16816(float* c, const uint32_t* a, const uint32_t* b) {
    asm volatile(
        "mma.sync.aligned.m16n8k16.row.col.f32.f16.f16.f32 "
        "{%0,%1,%2,%3},{%4,%5,%6,%7},{%8,%9},{%0,%1,%2,%3};"
        : "+f"(c[0]), "+f"(c[1]), "+f"(c[2]), "+f"(c[3])
        : "r"(a[0]), "r"(a[1]), "r"(a[2]), "r"(a[3]), "r"(b[0]), "r"(b[1]));
}
DI uint32_t swz(uint32_t byte_off, int rl) {  // XOR bit4 with bit2 of row index
    return byte_off ^ ((rl & 4) << 2);
}

// ---------------- prep kernels ----------------
__global__ void prep_x(const float* __restrict__ feat) {
    __shared__ float t[32][33];
    const int r = blockIdx.x, cit = blockIdx.y, b = blockIdx.z;
    const int col = threadIdx.x & 31, row8 = threadIdx.x >> 5;
#pragma unroll
    for (int it = 0; it < 4; it++) {
        int ci_l = row8 + it * 8;
        t[ci_l][col] = feat[(((size_t)b * CIN + cit * 32 + ci_l) * 32 + r) * 32 + col];
    }
    __syncthreads();
    const int ci = threadIdx.x & 31;
#pragma unroll
    for (int it = 0; it < 4; it++) {
        int cc = (threadIdx.x >> 5) + it * 8;
        float v = t[ci][cc];
        __half hi = __float2half_rn(v);
        __half lo = __float2half_rn(v - __half2float(hi));
        size_t o = ((size_t)b * NPOS + r * 32 + cc) * CIN + cit * 32 + ci;
        g_a_h[o] = hi;
        g_a_l[o] = lo;
    }
}
__global__ void prep_w1(const float* __restrict__ w1) {
    int t = blockIdx.x * 256 + threadIdx.x;  // 1024*512
    int co = t >> 9, ci = t & 511;
#pragma unroll
    for (int kk = 0; kk < 9; kk++) {
        float v = w1[((size_t)co * CIN + ci) * 9 + kk];
        __half hi = __float2half_rn(v);
        __half lo = __float2half_rn(v - __half2float(hi));
        size_t o = ((size_t)kk * CMID + co) * CIN + ci;
        g_w1_h[o] = hi;
        g_w1_l[o] = lo;
    }
}
__global__ void prep_w2(const float* __restrict__ w2) {
    int t = blockIdx.x * 256 + threadIdx.x;  // 512*1024
    int co = t >> 10, ci = t & 1023;
    float v = (co < CO2) ? w2[(size_t)co * CMID + ci] : 0.f;
    __half hi = __float2half_rn(v);
    __half lo = __float2half_rn(v - __half2float(hi));
    g_w2_h[t] = hi;
    g_w2_l[t] = lo;
}

// ---------------- conv1: implicit 3x3 conv, fp16-split mma.sync -------------
// Block: M=256 pos (8 rows x 32 cols) x N=64 co; 256 thr (8 warps, 4m x 2n).
// 2 CTAs/SM: regs 2*256*128 = 64K, smem ~93.8KB/CTA.
// Input single-buffered (21760B); weights double-buffered (2 x 36864B).
static constexpr int C1_IN_HALF = 10880;   // per split: 10*34*16*2
static constexpr int C1_WOFF = 21760;
static constexpr int C1_WSTAGE = 36864;    // 9kk*2split*64co*16ci*2B
static constexpr int C1_SCOFF = C1_WOFF + 2 * C1_WSTAGE;  // 95488
static constexpr int C1_SMEM = C1_SCOFF + 512;            // 96000

__global__ void __launch_bounds__(256, 2)
conv1_mma(const float* __restrict__ gamma, const float* __restrict__ beta,
          const float* __restrict__ mean, const float* __restrict__ var) {
    extern __shared__ __align__(16) char smem[];
    const uint32_t sb = smem_u32(smem);
    const int tid = threadIdx.x, lane = tid & 31, wid = tid >> 5;
    const int b = blockIdx.z, co0 = blockIdx.y * 64, row0 = blockIdx.x * 8;
    float* s_sc = (float*)(smem + C1_SCOFF);
    float* s_sh = s_sc + 64;
    if (tid < 64) {
        float sc = gamma[co0 + tid] * rsqrtf(var[co0 + tid] + 1e-5f);
        s_sc[tid] = sc;
        s_sh[tid] = beta[co0 + tid] - mean[co0 + tid] * sc;
    }
    const int warp_m0 = (wid >> 1) * 64, warp_n0 = (wid & 1) * 32;
    const int aro = ((lane >> 3) & 1) * 8 + (lane & 7);
    const int ahalf = lane >> 4;
    int Lb[4];
#pragma unroll
    for (int mf = 0; mf < 4; mf++) {
        int m = warp_m0 + mf * 16 + aro;
        Lb[mf] = (m >> 5) * 34 + (m & 31);
    }
    const int bco = ((lane >> 4) << 3) + (lane & 7);
    const int bhalf = (lane >> 3) & 1;
    const uint32_t bbase = swz((uint32_t)(bco * 32 + bhalf * 16), bco);

    float acc[4][4][4];
#pragma unroll
    for (int i = 0; i < 4; i++)
#pragma unroll
        for (int j = 0; j < 4; j++)
#pragma unroll
            for (int k = 0; k < 4; k++) acc[i][j][k] = 0.f;

    auto load_input = [&](int ci0) {
        // 2 splits x 10 rows x 34 cols x 2 halves = 1360 x 16B
#pragma unroll
        for (int it = 0; it < 6; it++) {
            int u = tid + it * 256;
            if (u < 1360) {
                int split = u >= 680;
                int r2 = u - split * 680;
                int i = r2 / 68;
                int r3 = r2 - i * 68;
                int j = r3 >> 1, half = r3 & 1;
                int ri = row0 + i - 1, cix = j - 1;
                bool ok = (unsigned)ri < 32u && (unsigned)cix < 32u;
                const __half* g = split ? g_a_l : g_a_h;
                const __half* src =
                    ok ? g + (((size_t)b * NPOS + ri * 32 + cix) * CIN + ci0 + half * 8) : g;
                int rl = i * 34 + j;
                uint32_t d = sb + split * C1_IN_HALF +
                             swz((uint32_t)(rl * 32 + half * 16), rl);
                cp16(d, src, ok ? 16u : 0u);
            }
        }
    };
    auto load_weights = [&](int s, int ci0) {
        uint32_t wb = sb + C1_WOFF + s * C1_WSTAGE;
        // 9 kk x 2 splits x 64 co x 2 halves = 2304 x 16B
#pragma unroll
        for (int it = 0; it < 9; it++) {
            int u = tid + it * 256;
            int kk = u >> 8;
            int r2 = u & 255;
            int split = r2 >> 7;
            int r3 = r2 & 127;
            int co = r3 >> 1, half = r3 & 1;
            const __half* g = split ? g_w1_l : g_w1_h;
            const __half* src = g + (((size_t)kk * CMID + co0 + co) * CIN + ci0 + half * 8);
            uint32_t d = wb + (kk * 2 + split) * 2048 +
                         swz((uint32_t)(co * 32 + half * 16), co);
            cp16(d, src, 16u);
        }
    };

    load_input(0);
    load_weights(0, 0);
    cp_commit();

    for (int ch = 0; ch < 32; ch++) {
        cp_wait<0>();
        __syncthreads();
        if (ch < 31) {  // weights for ch+1 overlap with compute of ch
            load_weights((ch + 1) & 1, (ch + 1) * 16);
            cp_commit();
        }
        uint32_t wb = sb + C1_WOFF + (ch & 1) * C1_WSTAGE;
        uint32_t areg[4][4], bregH[4][2], bregL[4][2];
#pragma unroll
        for (int kk = 0; kk < 9; kk++) {
            const int D = (kk / 3) * 34 + (kk % 3);
            {
                uint32_t baseH = wb + (kk * 2) * 2048 + bbase;
                uint32_t baseL = baseH + 2048;
#pragma unroll
                for (int np = 0; np < 2; np++) {
                    uint32_t r0, r1, r2, r3;
                    ldm4(baseH + (uint32_t)((warp_n0 + np * 16) * 32), r0, r1, r2, r3);
                    bregH[np * 2][0] = r0; bregH[np * 2][1] = r1;
                    bregH[np * 2 + 1][0] = r2; bregH[np * 2 + 1][1] = r3;
                    ldm4(baseL + (uint32_t)((warp_n0 + np * 16) * 32), r0, r1, r2, r3);
                    bregL[np * 2][0] = r0; bregL[np * 2][1] = r1;
                    bregL[np * 2 + 1][0] = r2; bregL[np * 2 + 1][1] = r3;
                }
            }
            auto lda = [&](int split) {
                uint32_t base = sb + split * C1_IN_HALF;
#pragma unroll
                for (int mf = 0; mf < 4; mf++) {
                    int rl = Lb[mf] + D;
                    uint32_t ad = base + swz((uint32_t)(rl * 32 + ahalf * 16), rl);
                    ldm4(ad, areg[mf][0], areg[mf][1], areg[mf][2], areg[mf][3]);
                }
            };
            lda(0);  // A-hi
#pragma unroll
            for (int mf = 0; mf < 4; mf++)
#pragma unroll
                for (int nf = 0; nf < 4; nf++) mma16816(acc[mf][nf], areg[mf], bregH[nf]);
#pragma unroll
            for (int mf = 0; mf < 4; mf++)
#pragma unroll
                for (int nf = 0; nf < 4; nf++) mma16816(acc[mf][nf], areg[mf], bregL[nf]);
            lda(1);  // A-lo
#pragma unroll
            for (int mf = 0; mf < 4; mf++)
#pragma unroll
                for (int nf = 0; nf < 4; nf++) mma16816(acc[mf][nf], areg[mf], bregH[nf]);
        }
        __syncthreads();
        if (ch < 31) {  // input for ch+1 (single buffer, now safe to overwrite)
            load_input((ch + 1) * 16);
            cp_commit();
        }
    }

    // epilogue: BN + leaky, write fp16 hi/lo splits for conv2
    const int gq = lane >> 2, t4 = lane & 3;
#pragma unroll
    for (int mf = 0; mf < 4; mf++) {
#pragma unroll
        for (int nf = 0; nf < 4; nf++) {
            int n = warp_n0 + nf * 8 + t4 * 2;
            float sc0 = s_sc[n], sc1 = s_sc[n + 1];
            float sh0 = s_sh[n], sh1 = s_sh[n + 1];
#pragma unroll
            for (int rr = 0; rr < 2; rr++) {
                int m = warp_m0 + mf * 16 + gq + rr * 8;
                float v0 = acc[mf][nf][rr * 2] * sc0 + sh0;
                float v1 = acc[mf][nf][rr * 2 + 1] * sc1 + sh1;
                v0 = v0 > 0.f ? v0 : 0.1f * v0;
                v1 = v1 > 0.f ? v1 : 0.1f * v1;
                __half h0 = __float2half_rn(v0), h1 = __float2half_rn(v1);
                __half l0 = __float2half_rn(v0 - __half2float(h0));
                __half l1 = __float2half_rn(v1 - __half2float(h1));
                size_t idx =
                    ((size_t)b * NPOS + blockIdx.x * 256 + m) * CMID + co0 + n;
                *(__half2*)(g_x_h + idx) = __halves2half2(h0, h1);
                *(__half2*)(g_x_l + idx) = __halves2half2(l0, l1);
            }
        }
    }
}

// ---------------- conv2: 1x1 GEMM, fp16-split mma.sync ----------------------
// Block: M=256 x N=64; 256 thr (8 warps, 4m x 2n); double-buffered; 2 CTAs/SM.
static constexpr int C2_IN_SPLIT = 8192;        // 256*16*2
static constexpr int C2_WOFF = 16384;
static constexpr int C2_STAGE = 16384 + 4096;   // 20480
static constexpr int C2_SMEM = 2 * C2_STAGE + 256;

__global__ void __launch_bounds__(256, 2)
conv2_mma(const float* __restrict__ b2) {
    extern __shared__ __align__(16) char smem[];
    const uint32_t sb = smem_u32(smem);
    const int tid = threadIdx.x, lane = tid & 31, wid = tid >> 5;
    const int b = blockIdx.z, co0 = blockIdx.y * 64, m0 = blockIdx.x * 256;
    float* s_bias = (float*)(smem + 2 * C2_STAGE);
    if (tid < 64) s_bias[tid] = (co0 + tid < CO2) ? b2[co0 + tid] : 0.f;

    const int warp_m0 = (wid >> 1) * 64, warp_n0 = (wid & 1) * 32;
    const int aro = ((lane >> 3) & 1) * 8 + (lane & 7);
    const int ahalf = lane >> 4;
    const int bco = ((lane >> 4) << 3) + (lane & 7);
    const int bhalf = (lane >> 3) & 1;
    const uint32_t bbase = swz((uint32_t)(bco * 32 + bhalf * 16), bco);

    float acc[4][4][4];
#pragma unroll
    for (int i = 0; i < 4; i++)
#pragma unroll
        for (int j = 0; j < 4; j++)
#pragma unroll
            for (int k = 0; k < 4; k++) acc[i][j][k] = 0.f;

    auto load_stage = [&](int s, int ci0) {
        uint32_t st = sb + s * C2_STAGE;
#pragma unroll
        for (int it = 0; it < 4; it++) {  // input: 2x256x2 = 1024 units
            int u = tid + it * 256;
            int split = u >> 9;
            int r2 = u & 511;
            int m = r2 >> 1, half = r2 & 1;
            const __half* g = split ? g_x_l : g_x_h;
            const __half* src = g + (((size_t)b * NPOS + m0 + m) * CMID + ci0 + half * 8);
            uint32_t d = st + split * C2_IN_SPLIT + swz((uint32_t)(m * 32 + half * 16), m);
            cp16(d, src, 16u);
        }
        {  // weights: 2x64x2 = 256 units
            int u = tid;
            int split = u >> 7;
            int r3 = u & 127;
            int co = r3 >> 1, half = r3 & 1;
            const __half* g = split ? g_w2_l : g_w2_h;
            const __half* src = g + ((size_t)(co0 + co) * CMID + ci0 + half * 8);
            uint32_t d = st + C2_WOFF + split * 2048 +
                         swz((uint32_t)(co * 32 + half * 16), co);
            cp16(d, src, 16u);
        }
    };

    load_stage(0, 0);
    cp_commit();

    for (int ch = 0; ch < 64; ch++) {
        if (ch < 63) {
            load_stage((ch + 1) & 1, (ch + 1) * 16);
            cp_commit();
            cp_wait<1>();
        } else {
            cp_wait<0>();
        }
        __syncthreads();
        uint32_t st = sb + (ch & 1) * C2_STAGE;
        uint32_t areg[4][4], bregH[4][2], bregL[4][2];
        {
            uint32_t baseH = st + C2_WOFF + bbase;
            uint32_t baseL = baseH + 2048;
#pragma unroll
            for (int np = 0; np < 2; np++) {
                uint32_t r0, r1, r2, r3;
                ldm4(baseH + (uint32_t)((warp_n0 + np * 16) * 32), r0, r1, r2, r3);
                bregH[np * 2][0] = r0; bregH[np * 2][1] = r1;
                bregH[np * 2 + 1][0] = r2; bregH[np * 2 + 1][1] = r3;
                ldm4(baseL + (uint32_t)((warp_n0 + np * 16) * 32), r0, r1, r2, r3);
                bregL[np * 2][0] = r0; bregL[np * 2][1] = r1;
                bregL[np * 2 + 1][0] = r2; bregL[np * 2 + 1][1] = r3;
            }
        }
        auto lda = [&](int split) {
            uint32_t base = st + split * C2_IN_SPLIT;
#pragma unroll
            for (int mf = 0; mf < 4; mf++) {
                int m = warp_m0 + mf * 16 + aro;
                uint32_t ad = base + swz((uint32_t)(m * 32 + ahalf * 16), m);
                ldm4(ad, areg[mf][0], areg[mf][1], areg[mf][2], areg[mf][3]);
            }
        };
        lda(0);
#pragma unroll
        for (int mf = 0; mf < 4; mf++)
#pragma unroll
            for (int nf = 0; nf < 4; nf++) mma16816(acc[mf][nf], areg[mf], bregH[nf]);
#pragma unroll
        for (int mf = 0; mf < 4; mf++)
#pragma unroll
            for (int nf = 0; nf < 4; nf++) mma16816(acc[mf][nf], areg[mf], bregL[nf]);
        lda(1);
#pragma unroll
        for (int mf = 0; mf < 4; mf++)
#pragma unroll
            for (int nf = 0; nf < 4; nf++) mma16816(acc[mf][nf], areg[mf], bregH[nf]);
        __syncthreads();
    }

    const int gq = lane >> 2, t4 = lane & 3;
#pragma unroll
    for (int mf = 0; mf < 4; mf++) {
#pragma unroll
        for (int nf = 0; nf < 4; nf++) {
            int n = warp_n0 + nf * 8 + t4 * 2;
            float b0 = s_bias[n], b1 = s_bias[n + 1];
#pragma unroll
            for (int rr = 0; rr < 2; rr++) {
                int m = warp_m0 + mf * 16 + gq + rr * 8;
                float v0 = acc[mf][nf][rr * 2] + b0;
                float v1 = acc[mf][nf][rr * 2 + 1] + b1;
                size_t idx = ((size_t)b * NPOS + m0 + m) * 512 + co0 + n;
                *(float2*)(g_preds + idx) = make_float2(v0, v1);
            }
        }
    }
}

// ---------------- decode ----------------
__global__ void decode_kernel(float* __restrict__ out) {
    int t = blockIdx.x * 256 + threadIdx.x;
    int p = t & 1023, ba = t >> 10, a = ba % 5, b = ba / 5;
    const float* pr = g_preds + ((size_t)b * NPOS + p) * 512 + a * 85;
    float tx = pr[0], ty = pr[1], tw = pr[2], th = pr[3], to = pr[4];
    float m = -1e30f, ssum = 0.f;
    int arg = 0;
#pragma unroll 4
    for (int j = 0; j < 80; j++) {
        float l = pr[5 + j];
        if (l > m) { ssum = ssum * expf(m - l) + 1.f; m = l; arg = j; }
        else        ssum += expf(l - m);
    }
    float obj = 1.f / (1.f + expf(-to));
    float score = obj / ssum;
    float bx = 1.f / (1.f + expf(-tx));
    float by = 1.f / (1.f + expf(-ty));
    float bw = expf(fminf(tw, 8.f));
    float bh = expf(fminf(th, 8.f));
    float cx = (bx + (float)(p & 31)) * 32.f;
    float cy = (by + (float)(p >> 5)) * 32.f;
    float pw = c_anc_w[a] * bw, ph = c_anc_h[a] * bh;
    float x1 = fminf(fmaxf(cx - 0.5f * pw, 0.f), 1023.f);
    float y1 = fminf(fmaxf(cy - 0.5f * ph, 0.f), 1023.f);
    float x2 = fminf(fmaxf(cx + 0.5f * pw, 0.f), 1023.f);
    float y2 = fminf(fmaxf(cy + 0.5f * ph, 0.f), 1023.f);
    size_t n = (size_t)b * 5120 + (size_t)p * 5 + a;
    float* o5 = out + n * 5;
    o5[0] = x1; o5[1] = y1; o5[2] = x2; o5[3] = y2; o5[4] = score;
    out[(size_t)819200 + n] = (float)arg;
}

// ---------------- host ----------------
extern "C" void kernel_launch(void* const* d_in, const int* in_sizes, int n_in,
                              void* d_out, int out_size) {
    const float* feat = (const float*)d_in[0];
    const float* w1   = (const float*)d_in[1];
    const float* gam  = (const float*)d_in[2];
    const float* bet  = (const float*)d_in[3];
    const float* mean = (const float*)d_in[4];
    const float* var  = (const float*)d_in[5];
    const float* w2   = (const float*)d_in[6];
    const float* b2   = (const float*)d_in[7];
    float* out = (float*)d_out;

    static bool attr_done = false;
    if (!attr_done) {
        cudaFuncSetAttribute(conv1_mma, cudaFuncAttributeMaxDynamicSharedMemorySize, C1_SMEM);
        cudaFuncSetAttribute(conv2_mma, cudaFuncAttributeMaxDynamicSharedMemorySize, C2_SMEM);
        attr_done = true;
    }

    prep_x<<<dim3(32, 16, 32), 256>>>(feat);
    prep_w1<<<2048, 256>>>(w1);
    prep_w2<<<2048, 256>>>(w2);
    conv1_mma<<<dim3(4, 16, 32), 256, C1_SMEM>>>(gam, bet, mean, var);
    conv2_mma<<<dim3(4, 8, 32), 256, C2_SMEM>>>(b2);
    decode_kernel<<<640, 256>>>(out);
}